// round 5
// baseline (speedup 1.0000x reference)
#include <cuda_runtime.h>
#include <cuda_bf16.h>

// Fixed shapes: B=16, T=512, D=384, MAX_LEN=4096
#define LR_B       16
#define LR_T       512
#define LR_D4      96                        // float4 per row
#define LR_MAXLEN  4096
#define LR_NEXP    (LR_B * LR_MAXLEN * 384)  // 25,165,824 floats

// expand grid: interleaved roles via bid % 5
//   bid % 5 == 0 -> token block (8 token-warps)          : 1024 blocks
//   else         -> zero block (8 warps x 2 rows = 16)   : 4096 blocks
#define NB_EXPAND  5120

__device__ int g_cum[LR_B * LR_T];   // inclusive cumsum per batch
__device__ int g_mel[LR_B];

// ---------------------------------------------------------------------------
// Kernel A: shfl-based inclusive scan per batch (3 barriers).
// Also emits mel_lens (float) into the output tail.
// ---------------------------------------------------------------------------
__global__ void lr_scan_kernel(const int* __restrict__ durations,
                               float* __restrict__ out_tail) {
    __shared__ int wsum[16];
    const int b = blockIdx.x, t = threadIdx.x;
    const int lane = t & 31, warp = t >> 5;

    int v = durations[b * LR_T + t];
    #pragma unroll
    for (int off = 1; off < 32; off <<= 1) {
        int n = __shfl_up_sync(0xffffffffu, v, off);
        if (lane >= off) v += n;
    }
    if (lane == 31) wsum[warp] = v;
    __syncthreads();
    if (warp == 0 && lane < 16) {
        int s = wsum[lane];
        #pragma unroll
        for (int off = 1; off < 16; off <<= 1) {
            int n = __shfl_up_sync(0xffffu, s, off, 16);
            if (lane >= off) s += n;
        }
        wsum[lane] = s;
    }
    __syncthreads();

    g_cum[b * LR_T + t] = v + (warp ? wsum[warp - 1] : 0);
    if (t == 0) {
        const int mel = wsum[15];
        g_mel[b] = mel;
        if (out_tail) out_tail[b] = (float)mel;
    }
}

// ---------------------------------------------------------------------------
// Kernel B: expand, fine-grained (R2 structure) with interleaved roles.
//  token warp: 1 token; load row once (3x float4/lane), store dur times.
//  zero warp : 2 consecutive rows; write zeros where pos >= mel.
// Row ownership is disjoint (token warps cover pos < mel).
// ---------------------------------------------------------------------------
__global__ __launch_bounds__(256)
void lr_expand_kernel(const float4* __restrict__ enc,
                      float4*       __restrict__ out) {
    const int warp = threadIdx.x >> 5;
    const int lane = threadIdx.x & 31;
    const int bid  = blockIdx.x;
    const int q    = bid / 5;

    if (bid % 5 == 0) {
        // ---- token path: q in [0,1024) ----
        const int tok = q * 8 + warp;                 // 0..8191
        const int b   = tok >> 9;
        const int t   = tok & 511;

        const int end   = g_cum[tok];
        const int start = t ? g_cum[tok - 1] : 0;
        if (start >= end) return;                     // dur == 0

        const float4* src = enc + (size_t)tok * LR_D4;
        const float4 v0 = src[lane];
        const float4 v1 = src[lane + 32];
        const float4 v2 = src[lane + 64];

        float4* dst = out + ((size_t)(b << 12) + start) * LR_D4;
        for (int p = start; p < end; ++p, dst += LR_D4) {
            dst[lane]      = v0;
            dst[lane + 32] = v1;
            dst[lane + 64] = v2;
        }
    } else {
        // ---- zero path: zid in [0,4096), 16 rows per block ----
        const int zid  = bid - q - 1;                 // remove token slots
        const int r0   = zid * 16 + warp * 2;         // 2 rows per warp
        const int b    = r0 >> 12;
        const int pos0 = r0 & 4095;
        const int mel  = g_mel[b];
        if (pos0 + 1 < mel) return;                   // both rows valid

        const float4 z = make_float4(0.f, 0.f, 0.f, 0.f);
        float4* dst = out + (size_t)r0 * LR_D4;
        #pragma unroll
        for (int i = 0; i < 2; ++i, dst += LR_D4) {
            if (pos0 + i >= mel) {
                dst[lane]      = z;
                dst[lane + 32] = z;
                dst[lane + 64] = z;
            }
        }
    }
}

extern "C" void kernel_launch(void* const* d_in, const int* in_sizes, int n_in,
                              void* d_out, int out_size) {
    const float4* enc = (const float4*)d_in[0];
    const int* durations = (const int*)d_in[1];
    float* out = (float*)d_out;

    float* out_tail = (out_size >= LR_NEXP + LR_B) ? (out + LR_NEXP) : nullptr;

    lr_scan_kernel<<<LR_B, LR_T>>>(durations, out_tail);
    lr_expand_kernel<<<NB_EXPAND, 256>>>(enc, (float4*)out);
}

// round 10
// speedup vs baseline: 1.3769x; 1.3769x over previous
#include <cuda_runtime.h>
#include <cuda_bf16.h>
#include <cstdint>

// Fixed shapes: B=16, T=512, D=384, MAX_LEN=4096
#define LR_B       16
#define LR_T       512
#define LR_D       384
#define LR_MAXLEN  4096
#define LR_NEXP    (LR_B * LR_MAXLEN * LR_D)   // 25,165,824 floats

#define NTOK_BLK   1024                        // 8 token-warps per block
#define NZERO_BLK  8192                        // 8 zero-rows per block

__device__ int g_cum[LR_B * LR_T];
__device__ int g_mel[LR_B];

// ---- Blackwell 256-bit global load/store (sm_100+) ----------------------
__device__ __forceinline__ void ldg256(const float* p, uint32_t r[8]) {
    asm volatile("ld.global.nc.v8.b32 {%0,%1,%2,%3,%4,%5,%6,%7}, [%8];"
                 : "=r"(r[0]), "=r"(r[1]), "=r"(r[2]), "=r"(r[3]),
                   "=r"(r[4]), "=r"(r[5]), "=r"(r[6]), "=r"(r[7])
                 : "l"(p));
}
__device__ __forceinline__ void stg256(float* p, const uint32_t r[8]) {
    asm volatile("st.global.v8.b32 [%0], {%1,%2,%3,%4,%5,%6,%7,%8};"
                 :: "l"(p),
                    "r"(r[0]), "r"(r[1]), "r"(r[2]), "r"(r[3]),
                    "r"(r[4]), "r"(r[5]), "r"(r[6]), "r"(r[7])
                 : "memory");
}

// ---------------------------------------------------------------------------
// Kernel A: shfl-based inclusive scan per batch (3 barriers).
// ---------------------------------------------------------------------------
__global__ void lr_scan_kernel(const int* __restrict__ durations,
                               float* __restrict__ out_tail) {
    __shared__ int wsum[16];
    const int b = blockIdx.x, t = threadIdx.x;
    const int lane = t & 31, warp = t >> 5;

    int v = durations[b * LR_T + t];
    #pragma unroll
    for (int off = 1; off < 32; off <<= 1) {
        int n = __shfl_up_sync(0xffffffffu, v, off);
        if (lane >= off) v += n;
    }
    if (lane == 31) wsum[warp] = v;
    __syncthreads();
    if (warp == 0 && lane < 16) {
        int s = wsum[lane];
        #pragma unroll
        for (int off = 1; off < 16; off <<= 1) {
            int n = __shfl_up_sync(0xffffu, s, off, 16);
            if (lane >= off) s += n;
        }
        wsum[lane] = s;
    }
    __syncthreads();

    g_cum[b * LR_T + t] = v + (warp ? wsum[warp - 1] : 0);
    if (t == 0) {
        const int mel = wsum[15];
        g_mel[b] = mel;
        if (out_tail) out_tail[b] = (float)mel;
    }
}

// ---------------------------------------------------------------------------
// Kernel B: expand — exact R2 grid layout (token blocks then zero blocks),
// but rows moved with 1x STG.256 + 1x STG.128 per warp per row.
//  Row layout per warp: floats [0,256) via v8 (lane*8), floats [256,384)
//  via float4 (lane*4). Both regions 32B-aligned (row stride 1536 = 48*32).
// ---------------------------------------------------------------------------
__global__ __launch_bounds__(256)
void lr_expand_kernel(const float* __restrict__ enc,
                      float*       __restrict__ out) {
    const int warp = threadIdx.x >> 5;
    const int lane = threadIdx.x & 31;

    if (blockIdx.x < NTOK_BLK) {
        // ---- token path: 1 token per warp ----
        const int tok = blockIdx.x * 8 + warp;        // 0..8191
        const int b   = tok >> 9;
        const int t   = tok & 511;
        const int end   = g_cum[tok];
        const int start = t ? g_cum[tok - 1] : 0;
        if (start >= end) return;                     // dur == 0

        const float* src = enc + (size_t)tok * LR_D;
        uint32_t r[8];
        ldg256(src + lane * 8, r);
        const float4 r2 = __ldg((const float4*)(src + 256) + lane);

        float* dst = out + ((size_t)(b << 12) + start) * LR_D;
        for (int p = start; p < end; ++p, dst += LR_D) {
            stg256(dst + lane * 8, r);
            ((float4*)(dst + 256))[lane] = r2;
        }
    } else {
        // ---- zero path: 1 row per warp ----
        const int row = (blockIdx.x - NTOK_BLK) * 8 + warp;   // 0..65535
        const int b   = row >> 12;
        const int pos = row & 4095;
        if (pos < g_mel[b]) return;                   // token warps own it

        const uint32_t z[8] = {0,0,0,0,0,0,0,0};
        float* dst = out + (size_t)row * LR_D;
        stg256(dst + lane * 8, z);
        ((float4*)(dst + 256))[lane] = make_float4(0.f, 0.f, 0.f, 0.f);
    }
}

extern "C" void kernel_launch(void* const* d_in, const int* in_sizes, int n_in,
                              void* d_out, int out_size) {
    const float* enc = (const float*)d_in[0];
    const int* durations = (const int*)d_in[1];
    float* out = (float*)d_out;

    float* out_tail = (out_size >= LR_NEXP + LR_B) ? (out + LR_NEXP) : nullptr;

    lr_scan_kernel<<<LR_B, LR_T>>>(durations, out_tail);
    lr_expand_kernel<<<NTOK_BLK + NZERO_BLK, 256>>>(enc, out);
}